// round 16
// baseline (speedup 1.0000x reference)
#include <cuda_runtime.h>

// Fixed shapes
#define BATCH   262144
#define NIN     128
#define NMID    512
#define NCOLS   130                      // n_in + n_extra
#define GRID1   1024                     // one wave at 7 CTAs/SM
#define ROWS_PER_BLK (BATCH / GRID1)     // 256

// Scratch (device globals; allocation forbidden)
__device__ __align__(16) float g_partial[(NIN + 1) * GRID1]; // [col][block]
__device__ __align__(16) float g_o[NIN];

// ---------------------------------------------------------------------------
// Pass 1: weighted column sums. UNCHANGED from R14 (24.5us, best measured).
// ---------------------------------------------------------------------------
__global__ void __launch_bounds__(256, 7)
reduce_pass(const float* __restrict__ x, const float* __restrict__ w) {
    const int tid   = threadIdx.x;
    const int lane  = tid & 31;
    const int wp    = tid >> 5;           // warp 0..7
    const int sub   = lane >> 4;          // row parity 0/1
    const int chunk = lane & 15;          // 32B chunk within 512B row
    const int b     = blockIdx.x;
    const long rbase = (long)b * ROWS_PER_BLK + (long)wp * 32;

    const float* xp = x + (rbase + sub) * NIN + chunk * 8;
    const float* wbase = w + rbase + sub;

    float acc[8];
#pragma unroll
    for (int j = 0; j < 8; ++j) acc[j] = 0.0f;
    float wacc = 0.0f;

#pragma unroll
    for (int i = 0; i < 16; ++i) {        // 2 rows per iter, 32 rows total
        unsigned r0, r1, r2, r3, r4, r5, r6, r7;
        asm volatile(
            "ld.global.nc.L2::evict_first.v8.b32 {%0,%1,%2,%3,%4,%5,%6,%7}, [%8];"
            : "=r"(r0), "=r"(r1), "=r"(r2), "=r"(r3),
              "=r"(r4), "=r"(r5), "=r"(r6), "=r"(r7)
            : "l"(xp + (long)(2 * i) * NIN));
        const float wv = __ldg(wbase + 2 * i);
        acc[0] = fmaf(wv, __uint_as_float(r0), acc[0]);
        acc[1] = fmaf(wv, __uint_as_float(r1), acc[1]);
        acc[2] = fmaf(wv, __uint_as_float(r2), acc[2]);
        acc[3] = fmaf(wv, __uint_as_float(r3), acc[3]);
        acc[4] = fmaf(wv, __uint_as_float(r4), acc[4]);
        acc[5] = fmaf(wv, __uint_as_float(r5), acc[5]);
        acc[6] = fmaf(wv, __uint_as_float(r6), acc[6]);
        acc[7] = fmaf(wv, __uint_as_float(r7), acc[7]);
        wacc += wv;
    }

#pragma unroll
    for (int j = 0; j < 8; ++j)
        acc[j] += __shfl_xor_sync(0xffffffffu, acc[j], 16);
    wacc += __shfl_xor_sync(0xffffffffu, wacc, 16);

    __shared__ float s[8][NIN + 4];
    __shared__ float sw[8];
    if (sub == 0) {
#pragma unroll
        for (int j = 0; j < 8; ++j) s[wp][chunk * 8 + j] = acc[j];
        if (chunk == 0) sw[wp] = wacc;
    }
    __syncthreads();

    if (tid < NIN) {
        float v = 0.0f;
#pragma unroll
        for (int l = 0; l < 8; ++l) v += s[l][tid];
        g_partial[tid * GRID1 + b] = v;
    } else if (tid == NIN) {
        float v = 0.0f;
#pragma unroll
        for (int l = 0; l < 8; ++l) v += sw[l];
        g_partial[NIN * GRID1 + b] = v;
    }
}

// ---------------------------------------------------------------------------
// Middle kernel: colsum -> xbar; v = relu(W_in @ xbar); o = W_out @ v.
// NEW: prefetch.global.L2 for all W_in/W_out lines at kernel start — the W
// fetch (0.52MB, ~4128 lines) overlaps Phase A, so Phase B/C hit L2 instead
// of paying cold-DRAM latency per warp-row.
// ---------------------------------------------------------------------------
__global__ __launch_bounds__(1024) void mid_pass(const float* __restrict__ p,
                                                 const float* __restrict__ W_in,
                                                 const float* __restrict__ W_out) {
    __shared__ float part8[NIN * 8];
    __shared__ float colsum[NIN + 1];
    __shared__ float xbar[NCOLS];
    __shared__ float v[NMID];

    const int tid    = threadIdx.x;
    const int warpid = tid >> 5;
    const int lid    = tid & 31;

    // Prefetch W into L2 (no register results; overlaps Phase A below)
    {
        const char* wi = reinterpret_cast<const char*>(W_in);
        const char* wo = reinterpret_cast<const char*>(W_out);
        // W_in: 512*130*4 = 266240B -> 2080 lines; W_out: 262144B -> 2048 lines
#pragma unroll
        for (int r = 0; r < 3; ++r) {
            const int i = tid + r * 1024;
            if (i < 2080)
                asm volatile("prefetch.global.L2 [%0];" :: "l"(wi + (long)i * 128));
        }
#pragma unroll
        for (int r = 0; r < 2; ++r) {
            const int i = tid + r * 1024;
            if (i < 2048)
                asm volatile("prefetch.global.L2 [%0];" :: "l"(wo + (long)i * 128));
        }
    }

    // Phase A1: cols 0..127, 8 threads per column (f4 strided loads)
    {
        const int col = tid >> 3;        // 0..127
        const int k   = tid & 7;
        const float4* pp = reinterpret_cast<const float4*>(g_partial + col * GRID1);
        float4 s4 = make_float4(0.f, 0.f, 0.f, 0.f);
#pragma unroll 8
        for (int i = k; i < GRID1 / 4; i += 8) {
            float4 t = __ldg(pp + i);
            s4.x += t.x; s4.y += t.y; s4.z += t.z; s4.w += t.w;
        }
        part8[tid] = (s4.x + s4.y) + (s4.z + s4.w);
    }
    // Phase A1b: col 128 (w-sum) by warp 0
    if (warpid == 0) {
        const float4* pp = reinterpret_cast<const float4*>(g_partial + NIN * GRID1);
        float4 s4 = make_float4(0.f, 0.f, 0.f, 0.f);
#pragma unroll
        for (int i = lid; i < GRID1 / 4; i += 32) {
            float4 t = __ldg(pp + i);
            s4.x += t.x; s4.y += t.y; s4.z += t.z; s4.w += t.w;
        }
        float ws = (s4.x + s4.y) + (s4.z + s4.w);
#pragma unroll
        for (int off = 16; off > 0; off >>= 1)
            ws += __shfl_xor_sync(0xffffffffu, ws, off);
        if (lid == 0) colsum[NIN] = ws;
    }
    __syncthreads();
    if (tid < NIN) {
        const float* pr = part8 + tid * 8;
        float cs = ((pr[0] + pr[1]) + (pr[2] + pr[3])) +
                   ((pr[4] + pr[5]) + (pr[6] + pr[7]));
        colsum[tid] = cs;
    }
    __syncthreads();
    if (tid < NIN) {
        xbar[tid] = colsum[tid] / colsum[NIN];
    } else if (tid == NIN) {
        xbar[NIN]     = __ldg(p + 0);
        xbar[NIN + 1] = __ldg(p + 1);
    }
    __syncthreads();

    // Phase B: v[r] = relu(W_in[r,:] . xbar). 32 warps x 16 rows, 4 rows/step.
#pragma unroll
    for (int g = 0; g < 4; ++g) {
        const int r = warpid * 16 + g * 4;
        const float* w0 = W_in + (long)(r + 0) * NCOLS;
        const float* w1 = W_in + (long)(r + 1) * NCOLS;
        const float* w2 = W_in + (long)(r + 2) * NCOLS;
        const float* w3 = W_in + (long)(r + 3) * NCOLS;
        float a0 = 0.f, a1 = 0.f, a2 = 0.f, a3 = 0.f;
#pragma unroll
        for (int j = lid; j < NCOLS; j += 32) {
            const float xb = xbar[j];
            a0 = fmaf(__ldg(w0 + j), xb, a0);
            a1 = fmaf(__ldg(w1 + j), xb, a1);
            a2 = fmaf(__ldg(w2 + j), xb, a2);
            a3 = fmaf(__ldg(w3 + j), xb, a3);
        }
#pragma unroll
        for (int off = 16; off > 0; off >>= 1) {
            a0 += __shfl_xor_sync(0xffffffffu, a0, off);
            a1 += __shfl_xor_sync(0xffffffffu, a1, off);
            a2 += __shfl_xor_sync(0xffffffffu, a2, off);
            a3 += __shfl_xor_sync(0xffffffffu, a3, off);
        }
        if (lid == 0) {
            v[r + 0] = fmaxf(a0, 0.0f);
            v[r + 1] = fmaxf(a1, 0.0f);
            v[r + 2] = fmaxf(a2, 0.0f);
            v[r + 3] = fmaxf(a3, 0.0f);
        }
    }
    __syncthreads();

    // Phase C: g_o[c] = W_out[c,:] . v. 32 warps x 4 rows, 2 rows/step.
#pragma unroll
    for (int g = 0; g < 2; ++g) {
        const int c = warpid * 4 + g * 2;
        const float* w0 = W_out + (long)(c + 0) * NMID;
        const float* w1 = W_out + (long)(c + 1) * NMID;
        float a0 = 0.f, a1 = 0.f;
#pragma unroll
        for (int m = lid; m < NMID; m += 32) {
            const float vv = v[m];
            a0 = fmaf(__ldg(w0 + m), vv, a0);
            a1 = fmaf(__ldg(w1 + m), vv, a1);
        }
#pragma unroll
        for (int off = 16; off > 0; off >>= 1) {
            a0 += __shfl_xor_sync(0xffffffffu, a0, off);
            a1 += __shfl_xor_sync(0xffffffffu, a1, off);
        }
        if (lid == 0) {
            g_o[c + 0] = a0;
            g_o[c + 1] = a1;
        }
    }
}

// ---------------------------------------------------------------------------
// Pass 2: out = x + o. UNCHANGED from R14 (best measured): 4096 sequential
// blocks x 256 thr x 8 float4, __ldcs reads + __stcs stores.
// ---------------------------------------------------------------------------
#define ADD_BLOCKS   4096
#define F4_PER_BLOCK 2048                // 256 threads * 8

__global__ void __launch_bounds__(256)
add_pass(const float* __restrict__ x, float* __restrict__ out) {
    const int tid = threadIdx.x;
    const long blk  = (long)blockIdx.x;
    const long base = blk * F4_PER_BLOCK + tid;

    const float4 ov = *(reinterpret_cast<const float4*>(g_o) + (tid & 31));
    const float4* x4 = reinterpret_cast<const float4*>(x);
    float4* o4p = reinterpret_cast<float4*>(out);

    float4 r[8];
#pragma unroll
    for (int k = 0; k < 8; ++k)
        r[k] = __ldcs(x4 + base + (long)k * 256);
#pragma unroll
    for (int k = 0; k < 8; ++k) {
        r[k].x += ov.x; r[k].y += ov.y; r[k].z += ov.z; r[k].w += ov.w;
        __stcs(o4p + base + (long)k * 256, r[k]);
    }
}

// ---------------------------------------------------------------------------
extern "C" void kernel_launch(void* const* d_in, const int* in_sizes, int n_in,
                              void* d_out, int out_size) {
    const float* x     = (const float*)d_in[0];   // [262144,128]
    const float* w     = (const float*)d_in[1];   // [262144,1]
    const float* p     = (const float*)d_in[2];   // [1,2]
    const float* W_in  = (const float*)d_in[3];   // [512,130]
    const float* W_out = (const float*)d_in[4];   // [128,512]
    float* out = (float*)d_out;                   // [262144,128]

    reduce_pass<<<GRID1, 256>>>(x, w);
    mid_pass<<<1, 1024>>>(p, W_in, W_out);
    add_pass<<<ADD_BLOCKS, 256>>>(x, out);
}

// round 17
// speedup vs baseline: 1.0276x; 1.0276x over previous
#include <cuda_runtime.h>

// Fixed shapes
#define BATCH   262144
#define NIN     128
#define NMID    512
#define NCOLS   130                      // n_in + n_extra
#define GRID1   1024                     // one wave at 7 CTAs/SM
#define ROWS_PER_BLK (BATCH / GRID1)     // 256

// Scratch (device globals; allocation forbidden)
__device__ __align__(16) float g_partial[(NIN + 1) * GRID1]; // [col][block]
__device__ __align__(16) float g_o[NIN];

// ---------------------------------------------------------------------------
// Pass 1: weighted column sums. 1024 blocks x 256 thr, single wave at
// 7 CTAs/SM. Warp covers 2 rows per 256-bit evict_first load; row-parity
// halves folded by shfl_xor(16). Best measured: 24.4-24.5us @ ~71% DRAM
// (the chip's @NAT streaming plateau for this pattern).
// ---------------------------------------------------------------------------
__global__ void __launch_bounds__(256, 7)
reduce_pass(const float* __restrict__ x, const float* __restrict__ w) {
    const int tid   = threadIdx.x;
    const int lane  = tid & 31;
    const int wp    = tid >> 5;           // warp 0..7
    const int sub   = lane >> 4;          // row parity 0/1
    const int chunk = lane & 15;          // 32B chunk within 512B row
    const int b     = blockIdx.x;
    const long rbase = (long)b * ROWS_PER_BLK + (long)wp * 32;

    const float* xp = x + (rbase + sub) * NIN + chunk * 8;
    const float* wbase = w + rbase + sub;

    float acc[8];
#pragma unroll
    for (int j = 0; j < 8; ++j) acc[j] = 0.0f;
    float wacc = 0.0f;

#pragma unroll
    for (int i = 0; i < 16; ++i) {        // 2 rows per iter, 32 rows total
        unsigned r0, r1, r2, r3, r4, r5, r6, r7;
        asm volatile(
            "ld.global.nc.L2::evict_first.v8.b32 {%0,%1,%2,%3,%4,%5,%6,%7}, [%8];"
            : "=r"(r0), "=r"(r1), "=r"(r2), "=r"(r3),
              "=r"(r4), "=r"(r5), "=r"(r6), "=r"(r7)
            : "l"(xp + (long)(2 * i) * NIN));
        const float wv = __ldg(wbase + 2 * i);
        acc[0] = fmaf(wv, __uint_as_float(r0), acc[0]);
        acc[1] = fmaf(wv, __uint_as_float(r1), acc[1]);
        acc[2] = fmaf(wv, __uint_as_float(r2), acc[2]);
        acc[3] = fmaf(wv, __uint_as_float(r3), acc[3]);
        acc[4] = fmaf(wv, __uint_as_float(r4), acc[4]);
        acc[5] = fmaf(wv, __uint_as_float(r5), acc[5]);
        acc[6] = fmaf(wv, __uint_as_float(r6), acc[6]);
        acc[7] = fmaf(wv, __uint_as_float(r7), acc[7]);
        wacc += wv;
    }

#pragma unroll
    for (int j = 0; j < 8; ++j)
        acc[j] += __shfl_xor_sync(0xffffffffu, acc[j], 16);
    wacc += __shfl_xor_sync(0xffffffffu, wacc, 16);

    __shared__ float s[8][NIN + 4];
    __shared__ float sw[8];
    if (sub == 0) {
#pragma unroll
        for (int j = 0; j < 8; ++j) s[wp][chunk * 8 + j] = acc[j];
        if (chunk == 0) sw[wp] = wacc;
    }
    __syncthreads();

    if (tid < NIN) {
        float v = 0.0f;
#pragma unroll
        for (int l = 0; l < 8; ++l) v += s[l][tid];
        g_partial[tid * GRID1 + b] = v;
    } else if (tid == NIN) {
        float v = 0.0f;
#pragma unroll
        for (int l = 0; l < 8; ++l) v += sw[l];
        g_partial[NIN * GRID1 + b] = v;
    }
}

// ---------------------------------------------------------------------------
// Middle kernel: colsum -> xbar; v = relu(W_in @ xbar); o = W_out @ v.
// One block, 1024 threads. The algebraic key: the second weighted average
// in the reference is the identity on a [1,NIN] row, and the weighted mean
// of the broadcast nuisance columns is the columns themselves.
// ---------------------------------------------------------------------------
__global__ __launch_bounds__(1024) void mid_pass(const float* __restrict__ p,
                                                 const float* __restrict__ W_in,
                                                 const float* __restrict__ W_out) {
    __shared__ float part8[NIN * 8];
    __shared__ float colsum[NIN + 1];
    __shared__ float xbar[NCOLS];
    __shared__ float v[NMID];

    const int tid    = threadIdx.x;
    const int warpid = tid >> 5;
    const int lid    = tid & 31;

    // Phase A1: cols 0..127, 8 threads per column (f4 strided loads)
    {
        const int col = tid >> 3;        // 0..127
        const int k   = tid & 7;
        const float4* pp = reinterpret_cast<const float4*>(g_partial + col * GRID1);
        float4 s4 = make_float4(0.f, 0.f, 0.f, 0.f);
#pragma unroll 8
        for (int i = k; i < GRID1 / 4; i += 8) {
            float4 t = __ldg(pp + i);
            s4.x += t.x; s4.y += t.y; s4.z += t.z; s4.w += t.w;
        }
        part8[tid] = (s4.x + s4.y) + (s4.z + s4.w);
    }
    // Phase A1b: col 128 (w-sum) by warp 0
    if (warpid == 0) {
        const float4* pp = reinterpret_cast<const float4*>(g_partial + NIN * GRID1);
        float4 s4 = make_float4(0.f, 0.f, 0.f, 0.f);
#pragma unroll
        for (int i = lid; i < GRID1 / 4; i += 32) {
            float4 t = __ldg(pp + i);
            s4.x += t.x; s4.y += t.y; s4.z += t.z; s4.w += t.w;
        }
        float ws = (s4.x + s4.y) + (s4.z + s4.w);
#pragma unroll
        for (int off = 16; off > 0; off >>= 1)
            ws += __shfl_xor_sync(0xffffffffu, ws, off);
        if (lid == 0) colsum[NIN] = ws;
    }
    __syncthreads();
    if (tid < NIN) {
        const float* pr = part8 + tid * 8;
        float cs = ((pr[0] + pr[1]) + (pr[2] + pr[3])) +
                   ((pr[4] + pr[5]) + (pr[6] + pr[7]));
        colsum[tid] = cs;
    }
    __syncthreads();
    if (tid < NIN) {
        xbar[tid] = colsum[tid] / colsum[NIN];
    } else if (tid == NIN) {
        xbar[NIN]     = __ldg(p + 0);
        xbar[NIN + 1] = __ldg(p + 1);
    }
    __syncthreads();

    // Phase B: v[r] = relu(W_in[r,:] . xbar). 32 warps x 16 rows, 4 rows/step.
#pragma unroll
    for (int g = 0; g < 4; ++g) {
        const int r = warpid * 16 + g * 4;
        const float* w0 = W_in + (long)(r + 0) * NCOLS;
        const float* w1 = W_in + (long)(r + 1) * NCOLS;
        const float* w2 = W_in + (long)(r + 2) * NCOLS;
        const float* w3 = W_in + (long)(r + 3) * NCOLS;
        float a0 = 0.f, a1 = 0.f, a2 = 0.f, a3 = 0.f;
#pragma unroll
        for (int j = lid; j < NCOLS; j += 32) {
            const float xb = xbar[j];
            a0 = fmaf(__ldg(w0 + j), xb, a0);
            a1 = fmaf(__ldg(w1 + j), xb, a1);
            a2 = fmaf(__ldg(w2 + j), xb, a2);
            a3 = fmaf(__ldg(w3 + j), xb, a3);
        }
#pragma unroll
        for (int off = 16; off > 0; off >>= 1) {
            a0 += __shfl_xor_sync(0xffffffffu, a0, off);
            a1 += __shfl_xor_sync(0xffffffffu, a1, off);
            a2 += __shfl_xor_sync(0xffffffffu, a2, off);
            a3 += __shfl_xor_sync(0xffffffffu, a3, off);
        }
        if (lid == 0) {
            v[r + 0] = fmaxf(a0, 0.0f);
            v[r + 1] = fmaxf(a1, 0.0f);
            v[r + 2] = fmaxf(a2, 0.0f);
            v[r + 3] = fmaxf(a3, 0.0f);
        }
    }
    __syncthreads();

    // Phase C: g_o[c] = W_out[c,:] . v. 32 warps x 4 rows, 2 rows/step.
#pragma unroll
    for (int g = 0; g < 2; ++g) {
        const int c = warpid * 4 + g * 2;
        const float* w0 = W_out + (long)(c + 0) * NMID;
        const float* w1 = W_out + (long)(c + 1) * NMID;
        float a0 = 0.f, a1 = 0.f;
#pragma unroll
        for (int m = lid; m < NMID; m += 32) {
            const float vv = v[m];
            a0 = fmaf(__ldg(w0 + m), vv, a0);
            a1 = fmaf(__ldg(w1 + m), vv, a1);
        }
#pragma unroll
        for (int off = 16; off > 0; off >>= 1) {
            a0 += __shfl_xor_sync(0xffffffffu, a0, off);
            a1 += __shfl_xor_sync(0xffffffffu, a1, off);
        }
        if (lid == 0) {
            g_o[c + 0] = a0;
            g_o[c + 1] = a1;
        }
    }
}

// ---------------------------------------------------------------------------
// Pass 2: out = x + o. Best measured: 4096 sequential blocks x 256 thr x
// 8 float4, __ldcs reads (evict-first: x is read once) + __stcs stores
// (streaming: out never re-read). Broadcast row element is loop-invariant
// per thread (stride is a multiple of 32 float4).
// ---------------------------------------------------------------------------
#define ADD_BLOCKS   4096
#define F4_PER_BLOCK 2048                // 256 threads * 8

__global__ void __launch_bounds__(256)
add_pass(const float* __restrict__ x, float* __restrict__ out) {
    const int tid = threadIdx.x;
    const long blk  = (long)blockIdx.x;
    const long base = blk * F4_PER_BLOCK + tid;

    const float4 ov = *(reinterpret_cast<const float4*>(g_o) + (tid & 31));
    const float4* x4 = reinterpret_cast<const float4*>(x);
    float4* o4p = reinterpret_cast<float4*>(out);

    float4 r[8];
#pragma unroll
    for (int k = 0; k < 8; ++k)
        r[k] = __ldcs(x4 + base + (long)k * 256);
#pragma unroll
    for (int k = 0; k < 8; ++k) {
        r[k].x += ov.x; r[k].y += ov.y; r[k].z += ov.z; r[k].w += ov.w;
        __stcs(o4p + base + (long)k * 256, r[k]);
    }
}

// ---------------------------------------------------------------------------
extern "C" void kernel_launch(void* const* d_in, const int* in_sizes, int n_in,
                              void* d_out, int out_size) {
    const float* x     = (const float*)d_in[0];   // [262144,128]
    const float* w     = (const float*)d_in[1];   // [262144,1]
    const float* p     = (const float*)d_in[2];   // [1,2]
    const float* W_in  = (const float*)d_in[3];   // [512,130]
    const float* W_out = (const float*)d_in[4];   // [128,512]
    float* out = (float*)d_out;                   // [262144,128]

    reduce_pass<<<GRID1, 256>>>(x, w);
    mid_pass<<<1, 1024>>>(p, W_in, W_out);
    add_pass<<<ADD_BLOCKS, 256>>>(x, out);
}